// round 16
// baseline (speedup 1.0000x reference)
#include <cuda_runtime.h>
#include <cstdint>

#define B_   64
#define T_   2048
#define H_   512
#define E_   256
#define V_   50000
#define G4H_ 2048

// ---------------- scratch (allocation-free: device globals) ----------------
__device__ float g_embg[B_ * E_];
__device__ float g_dec[B_ * H_];
__device__ float g_scores[B_ * T_];
__device__ float g_ctx[B_ * H_];
__device__ float g_ctxp[16 * B_ * H_];       // 16 tiles/b x 64 b x 512 h partial ctx (scaled)
__device__ float g_ml[B_ * 16 * 2];          // per-tile (m, l)
__device__ float g_gates[B_ * G4H_];
__device__ float g_wencr[H_ * H_];           // tf32-rounded W_enc

// ---------------- helpers ----------------
__device__ __forceinline__ uint32_t smem_u32(const void* p) {
    uint32_t a;
    asm("{ .reg .u64 t; cvta.to.shared.u64 t, %1; cvt.u32.u64 %0, t; }" : "=r"(a) : "l"(p));
    return a;
}
__device__ __forceinline__ void cpa16(uint32_t s, const void* g) {
    asm volatile("cp.async.cg.shared.global [%0], [%1], 16;" :: "r"(s), "l"(g));
}
__device__ __forceinline__ void cpa_commit() {
    asm volatile("cp.async.commit_group;" ::: "memory");
}
__device__ __forceinline__ void cpa_wait1() {
    asm volatile("cp.async.wait_group 1;" ::: "memory");
}
__device__ __forceinline__ void cpa_wait0() {
    asm volatile("cp.async.wait_group 0;" ::: "memory");
}
__device__ __forceinline__ uint32_t ldtf32(const float* p) {
    uint32_t y; asm("cvt.rna.tf32.f32 %0, %1;" : "=r"(y) : "f"(*p));
    return y;
}
__device__ __forceinline__ void mma8(float* c, const uint32_t* a, uint32_t b0, uint32_t b1) {
    asm volatile(
        "mma.sync.aligned.m16n8k8.row.col.f32.tf32.tf32.f32 "
        "{%0,%1,%2,%3},{%4,%5,%6,%7},{%8,%9},{%0,%1,%2,%3};"
        : "+f"(c[0]), "+f"(c[1]), "+f"(c[2]), "+f"(c[3])
        : "r"(a[0]), "r"(a[1]), "r"(a[2]), "r"(a[3]), "r"(b0), "r"(b1));
}

// ---------------- transcendentals ----------------
__device__ __forceinline__ float tanh_fast(float x) {
    float e = __expf(2.f * x);
    return 1.f - __fdividef(2.f, e + 1.f);
}
__device__ __forceinline__ float sig_fast(float x) {
    return __fdividef(1.f, 1.f + __expf(-x));
}

extern __shared__ __align__(16) char dsm[];

// ================= k_energy_mma =================
// scores[b,t] = sum_h v[h] * tanh( [enc @ Wenc^T](t,h) + dec[b,h] )
// Also: per-tile softmax stats (m,l) + partial context (flash-style).
// CTA: 128 rows (t), N-chunks of 128 (h) x4, K=512 in chunks of 32 (cp.async dbuf).
#define ESTR  36
#define E_A0  0
#define E_A1  18432
#define E_B0  36864
#define E_B1  55296
#define E_DV  73728
#define E_VV  75776
#define E_SR  77824
#define E_W   78848
#define E_R8  79360
#define E_SMEM 79424

__global__ void __launch_bounds__(256, 2) k_energy_mma(
    const float* __restrict__ enc, const float* __restrict__ vat)
{
    uint32_t sb = smem_u32(dsm);
    int tid = threadIdx.x, wid = tid >> 5, lane = tid & 31;
    int wm = wid & 3, wn = wid >> 2;       // 4 m-warps x 2 n-warps
    int q = lane >> 2, c4 = lane & 3;
    int m0 = blockIdx.x * 128;
    int b  = m0 >> 11;
    int bi = blockIdx.x;                   // b*16 + tile

    float* dv = (float*)(dsm + E_DV);
    float* vv = (float*)(dsm + E_VV);
    for (int i = tid; i < H_; i += 256) { dv[i] = g_dec[b * H_ + i]; vv[i] = vat[i]; }

    const uint32_t Ao[2] = {sb + E_A0, sb + E_A1};
    const uint32_t Bo[2] = {sb + E_B0, sb + E_B1};

    float sp[4] = {0.f, 0.f, 0.f, 0.f};
    __syncthreads();

    #pragma unroll 1
    for (int c0 = 0; c0 < H_; c0 += 128) {
        float acc[2][8][4];
        #pragma unroll
        for (int mi = 0; mi < 2; mi++)
            #pragma unroll
            for (int nj = 0; nj < 8; nj++)
                #pragma unroll
                for (int e = 0; e < 4; e++) acc[mi][nj][e] = 0.f;

        // preload chunk 0
        #pragma unroll
        for (int i = 0; i < 4; i++) {
            int idx = tid + i * 256, r = idx >> 3, c = idx & 7;
            cpa16(Ao[0] + (uint32_t)(r * ESTR + c * 4) * 4,
                  enc + (size_t)(m0 + r) * H_ + c * 4);
            cpa16(Bo[0] + (uint32_t)(r * ESTR + c * 4) * 4,
                  g_wencr + (size_t)(c0 + r) * H_ + c * 4);
        }
        cpa_commit();

        #pragma unroll 1
        for (int s = 0; s < 16; s++) {
            if (s < 15) {
                int kc = (s + 1) * 32, nb = (s + 1) & 1;
                #pragma unroll
                for (int i = 0; i < 4; i++) {
                    int idx = tid + i * 256, r = idx >> 3, c = idx & 7;
                    cpa16(Ao[nb] + (uint32_t)(r * ESTR + c * 4) * 4,
                          enc + (size_t)(m0 + r) * H_ + kc + c * 4);
                    cpa16(Bo[nb] + (uint32_t)(r * ESTR + c * 4) * 4,
                          g_wencr + (size_t)(c0 + r) * H_ + kc + c * 4);
                }
                cpa_commit();
                cpa_wait1();
            } else {
                cpa_wait0();
            }
            __syncthreads();

            const float* As = (const float*)(dsm + (((s & 1) ? E_A1 : E_A0)));
            const float* Bs = (const float*)(dsm + (((s & 1) ? E_B1 : E_B0)));
            #pragma unroll
            for (int k = 0; k < 32; k += 8) {
                uint32_t a[2][4];
                #pragma unroll
                for (int mi = 0; mi < 2; mi++) {
                    int r0 = wm * 32 + mi * 16 + q;
                    a[mi][0] = ldtf32(&As[r0 * ESTR + k + c4]);
                    a[mi][1] = ldtf32(&As[(r0 + 8) * ESTR + k + c4]);
                    a[mi][2] = ldtf32(&As[r0 * ESTR + k + c4 + 4]);
                    a[mi][3] = ldtf32(&As[(r0 + 8) * ESTR + k + c4 + 4]);
                }
                #pragma unroll
                for (int nj = 0; nj < 8; nj++) {
                    int nr = wn * 64 + nj * 8 + q;
                    uint32_t b0 = __float_as_uint(Bs[nr * ESTR + k + c4]);
                    uint32_t b1 = __float_as_uint(Bs[nr * ESTR + k + c4 + 4]);
                    mma8(acc[0][nj], a[0], b0, b1);
                    mma8(acc[1][nj], a[1], b0, b1);
                }
            }
            __syncthreads();
        }

        // fused epilogue for this N-chunk: tanh + v-weighted partial sums
        #pragma unroll
        for (int mi = 0; mi < 2; mi++) {
            #pragma unroll
            for (int nj = 0; nj < 8; nj++) {
                #pragma unroll
                for (int e = 0; e < 4; e++) {
                    int col = c0 + wn * 64 + nj * 8 + 2 * c4 + (e & 1);
                    float t = tanh_fast(acc[mi][nj][e] + dv[col]);
                    sp[mi * 2 + (e >> 1)] += t * vv[col];
                }
            }
        }
    }

    // reduce over the quad (4 lanes hold different columns)
    #pragma unroll
    for (int i = 0; i < 4; i++) {
        sp[i] += __shfl_xor_sync(0xffffffffu, sp[i], 1);
        sp[i] += __shfl_xor_sync(0xffffffffu, sp[i], 2);
    }
    float* sred = (float*)(dsm + E_SR);
    float* wbuf = (float*)(dsm + E_W);
    float* r8   = (float*)(dsm + E_R8);
    if (c4 == 0) {
        #pragma unroll
        for (int mi = 0; mi < 2; mi++)
            #pragma unroll
            for (int o8 = 0; o8 < 2; o8++) {
                int r = wm * 32 + mi * 16 + o8 * 8 + q;
                sred[wn * 128 + r] = sp[mi * 2 + o8];
            }
    }
    __syncthreads();

    // ---- flash-style stats + partial context ----
    float s = 0.f;
    if (tid < 128) {
        s = sred[tid] + sred[128 + tid];
        g_scores[m0 + tid] = s;
        float m = s;
        #pragma unroll
        for (int o = 16; o; o >>= 1) m = fmaxf(m, __shfl_xor_sync(0xffffffffu, m, o));
        if (lane == 0) r8[wid] = m;
    }
    __syncthreads();
    float mt = fmaxf(fmaxf(r8[0], r8[1]), fmaxf(r8[2], r8[3]));
    if (tid < 128) {
        float w = __expf(s - mt);
        wbuf[tid] = w;
        float l = w;
        #pragma unroll
        for (int o = 16; o; o >>= 1) l += __shfl_xor_sync(0xffffffffu, l, o);
        if (lane == 0) r8[4 + wid] = l;
    }
    __syncthreads();
    if (tid == 0) {
        g_ml[bi * 2 + 0] = mt;
        g_ml[bi * 2 + 1] = r8[4] + r8[5] + r8[6] + r8[7];
    }
    // partial context: ctxp[h] = sum_t w_t * enc[m0+t, h]; 256 threads x float2
    {
        float2 acc = make_float2(0.f, 0.f);
        const float* ep = enc + (size_t)m0 * H_ + tid * 2;
        #pragma unroll 4
        for (int t = 0; t < 128; t++) {
            float wv = wbuf[t];
            float2 e = *(const float2*)(ep + (size_t)t * H_);
            acc.x += wv * e.x; acc.y += wv * e.y;
        }
        *(float2*)(&g_ctxp[(size_t)bi * H_ + tid * 2]) = acc;
    }
}

// ================= k_attnctx =================
// Per batch b: combine 16 tile (m,l,ctxp) -> global softmax attn + context.
__global__ void k_attnctx(const float* __restrict__ enc, float* __restrict__ attn) {
    int b = blockIdx.x, tid = threadIdx.x;  // 256
    __shared__ float sm_m[16], sm_l[16], sML[2];
    if (tid < 16) {
        sm_m[tid] = g_ml[(b * 16 + tid) * 2 + 0];
        sm_l[tid] = g_ml[(b * 16 + tid) * 2 + 1];
    }
    __syncthreads();
    if (tid == 0) {
        float M = sm_m[0];
        #pragma unroll
        for (int i = 1; i < 16; i++) M = fmaxf(M, sm_m[i]);
        float L = 0.f;
        #pragma unroll
        for (int i = 0; i < 16; i++) L += sm_l[i] * __expf(sm_m[i] - M);
        sML[0] = M; sML[1] = L;
    }
    __syncthreads();
    float M = sML[0];
    float invL = __fdividef(1.f, sML[1]);
    for (int t = tid; t < T_; t += 256)
        attn[b * T_ + t] = __expf(g_scores[b * T_ + t] - M) * invL;
    for (int h = tid; h < H_; h += 256) {
        float acc = 0.f;
        #pragma unroll
        for (int i = 0; i < 16; i++)
            acc += __expf(sm_m[i] - M) * g_ctxp[(size_t)(b * 16 + i) * H_ + h];
        g_ctx[b * H_ + h] = acc * invL;
    }
}

// ================= k_logits_mma =================
// logits = [h_new || ctx](64x1024) @ W_out^T + b_out.  N-tile 128 of V, K=1024.
#define L_A0  0
#define L_A1  9216
#define L_B0  18432
#define L_B1  36864
#define L_SMEM 55296

__global__ void __launch_bounds__(256, 2) k_logits_mma(
    const float* __restrict__ hnew, const float* __restrict__ Wout,
    const float* __restrict__ bout, float* __restrict__ out)
{
    uint32_t sb = smem_u32(dsm);
    int tid = threadIdx.x, wid = tid >> 5, lane = tid & 31;
    int wm = wid & 1, wn = wid >> 1;       // 2 m-warps x 4 n-warps
    int q = lane >> 2, c4 = lane & 3;
    int v0 = blockIdx.x * 128;

    const uint32_t Ao[2] = {sb + L_A0, sb + L_A1};
    const uint32_t Bo[2] = {sb + L_B0, sb + L_B1};

    float acc[2][4][4];
    #pragma unroll
    for (int mi = 0; mi < 2; mi++)
        #pragma unroll
        for (int nj = 0; nj < 4; nj++)
            #pragma unroll
            for (int e = 0; e < 4; e++) acc[mi][nj][e] = 0.f;

    #define L_LOAD(buf, kc) do {                                                   \
        const float* asrc = ((kc) < 512) ? (hnew + (kc)) : (g_ctx + (kc) - 512);   \
        {   int idx = tid, r = idx >> 3, c = idx & 7;                              \
            cpa16(Ao[buf] + (uint32_t)(r * ESTR + c * 4) * 4,                      \
                  asrc + (size_t)r * H_ + c * 4);                                  \
            idx = tid + 256; r = idx >> 3; c = idx & 7;                            \
            cpa16(Ao[buf] + (uint32_t)(r * ESTR + c * 4) * 4,                      \
                  asrc + (size_t)r * H_ + c * 4); }                                \
        _Pragma("unroll")                                                          \
        for (int i = 0; i < 4; i++) {                                              \
            int idx = tid + i * 256, r = idx >> 3, c = idx & 7;                    \
            int v = v0 + r;                                                        \
            uint32_t sa = Bo[buf] + (uint32_t)(r * ESTR + c * 4) * 4;              \
            if (v < V_) cpa16(sa, Wout + (size_t)v * 1024 + (kc) + c * 4);         \
            else { float4 z = make_float4(0.f,0.f,0.f,0.f);                        \
                   *(float4*)(dsm + (sa - sb)) = z; }                              \
        }                                                                          \
    } while (0)

    L_LOAD(0, 0);
    cpa_commit();

    #pragma unroll 1
    for (int s = 0; s < 32; s++) {
        if (s < 31) {
            int nb = (s + 1) & 1, kc = (s + 1) * 32;
            L_LOAD(nb, kc);
            cpa_commit();
            cpa_wait1();
        } else {
            cpa_wait0();
        }
        __syncthreads();

        const float* As = (const float*)(dsm + (((s & 1) ? L_A1 : L_A0)));
        const float* Bs = (const float*)(dsm + (((s & 1) ? L_B1 : L_B0)));
        #pragma unroll
        for (int k = 0; k < 32; k += 8) {
            uint32_t a[2][4];
            #pragma unroll
            for (int mi = 0; mi < 2; mi++) {
                int r0 = wm * 32 + mi * 16 + q;
                a[mi][0] = ldtf32(&As[r0 * ESTR + k + c4]);
                a[mi][1] = ldtf32(&As[(r0 + 8) * ESTR + k + c4]);
                a[mi][2] = ldtf32(&As[r0 * ESTR + k + c4 + 4]);
                a[mi][3] = ldtf32(&As[(r0 + 8) * ESTR + k + c4 + 4]);
            }
            #pragma unroll
            for (int nj = 0; nj < 4; nj++) {
                int nr = wn * 32 + nj * 8 + q;
                uint32_t b0 = ldtf32(&Bs[nr * ESTR + k + c4]);
                uint32_t b1 = ldtf32(&Bs[nr * ESTR + k + c4 + 4]);
                mma8(acc[0][nj], a[0], b0, b1);
                mma8(acc[1][nj], a[1], b0, b1);
            }
        }
        __syncthreads();
    }

    #pragma unroll
    for (int mi = 0; mi < 2; mi++) {
        #pragma unroll
        for (int nj = 0; nj < 4; nj++) {
            #pragma unroll
            for (int e = 0; e < 4; e++) {
                int row = wm * 32 + mi * 16 + ((e >> 1) ? q + 8 : q);
                int v = v0 + wn * 32 + nj * 8 + 2 * c4 + (e & 1);
                if (v < V_)
                    out[(size_t)row * V_ + v] = acc[mi][nj][e] + bout[v];
            }
        }
    }
    #undef L_LOAD
}

// ---------------- small kernels ----------------
__global__ void k_roundw(const float* __restrict__ Wenc) {
    int i = blockIdx.x * 1024 + threadIdx.x;
    uint32_t y; asm("cvt.rna.tf32.f32 %0, %1;" : "=r"(y) : "f"(Wenc[i]));
    g_wencr[i] = __uint_as_float(y);
}

__global__ void k_embed(const int* __restrict__ tok, const float* __restrict__ emb) {
    int b = blockIdx.x;
    g_embg[b * E_ + threadIdx.x] = emb[tok[b] * E_ + threadIdx.x];
}

__global__ void k_dec(const float* __restrict__ hidden, const float* __restrict__ Wdec) {
    int b = blockIdx.x;
    __shared__ float sh[H_];
    int tid = threadIdx.x;
    for (int i = tid; i < H_; i += 256) sh[i] = hidden[b * H_ + i];
    __syncthreads();
    int w = tid >> 5, lane = tid & 31;
    for (int h = w; h < H_; h += 8) {
        float acc = 0.f;
        for (int k = lane; k < H_; k += 32) acc += sh[k] * Wdec[h * H_ + k];
        #pragma unroll
        for (int o = 16; o; o >>= 1) acc += __shfl_down_sync(0xffffffffu, acc, o);
        if (!lane) g_dec[b * H_ + h] = acc;
    }
}

__global__ void k_gates(const float* __restrict__ Wih, const float* __restrict__ Whh,
                        const float* __restrict__ bih, const float* __restrict__ bhh,
                        const float* __restrict__ hidden) {
    int j = blockIdx.x;
    __shared__ float sw[1280];
    int tid = threadIdx.x;
    for (int i = tid; i < 768; i += 256) sw[i] = Wih[j * 768 + i];
    for (int i = tid; i < 512; i += 256) sw[768 + i] = Whh[j * 512 + i];
    __syncthreads();
    float bias = bih[j] + bhh[j];
    int w = tid >> 5, lane = tid & 31;
    for (int b = w; b < B_; b += 8) {
        float acc = 0.f;
        for (int k = lane; k < 256; k += 32) acc += sw[k] * g_embg[b * E_ + k];
        for (int k = lane; k < 512; k += 32)
            acc += sw[256 + k] * g_ctx[b * H_ + k] + sw[768 + k] * hidden[b * H_ + k];
        #pragma unroll
        for (int o = 16; o; o >>= 1) acc += __shfl_down_sync(0xffffffffu, acc, o);
        if (!lane) g_gates[b * G4H_ + j] = acc + bias;
    }
}

__global__ void k_lstm(const float* __restrict__ cell,
                       float* __restrict__ hout, float* __restrict__ cout) {
    int b = blockIdx.x, h = threadIdx.x;
    const float* g = g_gates + b * G4H_;
    float ig = sig_fast(g[h]);
    float fg = sig_fast(g[512 + h]);
    float gg = tanh_fast(g[1024 + h]);
    float og = sig_fast(g[1536 + h]);
    float cn = fg * cell[b * H_ + h] + ig * gg;
    float hn = og * tanh_fast(cn);
    cout[b * H_ + h] = cn;
    hout[b * H_ + h] = hn;
}

// ---------------- host launcher ----------------
extern "C" void kernel_launch(void* const* d_in, const int* in_sizes, int n_in,
                              void* d_out, int out_size) {
    const int*   tok    = (const int*)  d_in[0];
    const float* hidden = (const float*)d_in[1];
    const float* cell   = (const float*)d_in[2];
    const float* enc    = (const float*)d_in[3];
    const float* emb    = (const float*)d_in[4];
    const float* Wenc   = (const float*)d_in[5];
    const float* Wdec   = (const float*)d_in[6];
    const float* vat    = (const float*)d_in[7];
    const float* Wih    = (const float*)d_in[8];
    const float* Whh    = (const float*)d_in[9];
    const float* bih    = (const float*)d_in[10];
    const float* bhh    = (const float*)d_in[11];
    const float* Wout   = (const float*)d_in[12];
    const float* bout   = (const float*)d_in[13];

    float* out        = (float*)d_out;
    float* out_logits = out;
    float* out_h      = out_logits + (size_t)B_ * V_;
    float* out_c      = out_h + B_ * H_;
    float* out_attn   = out_c + B_ * H_;

    cudaFuncSetAttribute(k_energy_mma, cudaFuncAttributeMaxDynamicSharedMemorySize, E_SMEM);
    cudaFuncSetAttribute(k_logits_mma, cudaFuncAttributeMaxDynamicSharedMemorySize, L_SMEM);

    k_roundw    <<<(H_ * H_) / 1024, 1024>>>(Wenc);
    k_embed     <<<B_, E_>>>(tok, emb);
    k_dec       <<<B_, 256>>>(hidden, Wdec);
    k_energy_mma<<<(B_ * T_) / 128, 256, E_SMEM>>>(enc, vat);
    k_attnctx   <<<B_, 256>>>(enc, out_attn);
    k_gates     <<<G4H_, 256>>>(Wih, Whh, bih, bhh, hidden);
    k_lstm      <<<B_, H_>>>(cell, out_h, out_c);
    k_logits_mma<<<(V_ + 127) / 128, 256, L_SMEM>>>(out_h, Wout, bout, out_logits);
}